// round 1
// baseline (speedup 1.0000x reference)
#include <cuda_runtime.h>
#include <cuda_bf16.h>

// Fused MLP: [N,2] -> 64 -> 64 -> 64 -> 1 with chaotic logistic-map activation.
// Weights live in __constant__ memory so Blackwell ptxas emits LDCU -> UR and
// FFMA R,R,UR,R (2 distinct GPR reads -> rt_SMSP can hit 1 instead of 2).

#define RCONST 3.82843f

__constant__ float cW1[64 * 2];
__constant__ float cb1[64];
__constant__ float cW2[64 * 64];
__constant__ float cb2[64];
__constant__ float cW3[64 * 64];
__constant__ float cb3[64];
__constant__ float cW4[64];
__constant__ float cb4[1];

__device__ __forceinline__ float act(float x) {
    // cos squashing into [0,1], then two logistic-map iterations
    x = cosf(x) * 0.5f + 0.5f;
    x = RCONST * x * (1.0f - x);
    x = RCONST * x * (1.0f - x);
    return x;
}

// One 64x64 dense layer + activation, weights row-major W[j*64 + k].
__device__ __forceinline__ void layer64(float h[64], const float* __restrict__ W,
                                        const float* __restrict__ b) {
    float acc[64];
#pragma unroll
    for (int j = 0; j < 64; ++j) acc[j] = b[j];
    // k outer (unroll 4 so the 4 consecutive W[j*64+k..k+3] vectorize to LDCU.128),
    // j inner fully unrolled -> 64 independent FMA chains, plenty of ILP.
#pragma unroll 4
    for (int k = 0; k < 64; ++k) {
        const float hk = h[k];
#pragma unroll
        for (int j = 0; j < 64; ++j) {
            acc[j] = fmaf(hk, W[j * 64 + k], acc[j]);
        }
    }
#pragma unroll
    for (int j = 0; j < 64; ++j) h[j] = act(acc[j]);
}

__global__ void __launch_bounds__(128) Model_17188459119206_kernel(
    const float* __restrict__ x, float* __restrict__ out, int n) {
    const int i = blockIdx.x * 128 + threadIdx.x;
    if (i >= n) return;

    const float2 p = reinterpret_cast<const float2*>(x)[i];

    float h[64];
    // Layer 1: 2 -> 64
#pragma unroll
    for (int j = 0; j < 64; ++j) {
        float a = fmaf(cW1[2 * j], p.x, fmaf(cW1[2 * j + 1], p.y, cb1[j]));
        h[j] = act(a);
    }

    // Layers 2,3: 64 -> 64
    layer64(h, cW2, cb2);
    layer64(h, cW3, cb3);

    // Layer 4: 64 -> 1
    float o = cb4[0];
#pragma unroll
    for (int k = 0; k < 64; ++k) o = fmaf(h[k], cW4[k], o);
    out[i] = act(o);
}

extern "C" void kernel_launch(void* const* d_in, const int* in_sizes, int n_in,
                              void* d_out, int out_size) {
    // Input order (metadata): x, W1, b1, W2, b2, W3, b3, W4, b4
    const float* x = (const float*)d_in[0];
    const int n = in_sizes[0] / 2;  // x is [N, 2]

    // Stage all weights into constant memory (device-to-device, graph-capturable).
    cudaMemcpyToSymbolAsync(cW1, d_in[1], sizeof(float) * 64 * 2, 0, cudaMemcpyDeviceToDevice, 0);
    cudaMemcpyToSymbolAsync(cb1, d_in[2], sizeof(float) * 64,     0, cudaMemcpyDeviceToDevice, 0);
    cudaMemcpyToSymbolAsync(cW2, d_in[3], sizeof(float) * 64 * 64,0, cudaMemcpyDeviceToDevice, 0);
    cudaMemcpyToSymbolAsync(cb2, d_in[4], sizeof(float) * 64,     0, cudaMemcpyDeviceToDevice, 0);
    cudaMemcpyToSymbolAsync(cW3, d_in[5], sizeof(float) * 64 * 64,0, cudaMemcpyDeviceToDevice, 0);
    cudaMemcpyToSymbolAsync(cb3, d_in[6], sizeof(float) * 64,     0, cudaMemcpyDeviceToDevice, 0);
    cudaMemcpyToSymbolAsync(cW4, d_in[7], sizeof(float) * 64,     0, cudaMemcpyDeviceToDevice, 0);
    cudaMemcpyToSymbolAsync(cb4, d_in[8], sizeof(float) * 1,      0, cudaMemcpyDeviceToDevice, 0);

    const int threads = 128;
    const int blocks = (n + threads - 1) / threads;
    Model_17188459119206_kernel<<<blocks, threads>>>(x, (float*)d_out, n);
}

// round 3
// speedup vs baseline: 8.0475x; 8.0475x over previous
#include <cuda_runtime.h>

// Fused MLP [N,2] -> 64 -> 64 -> 64 -> 1, chaotic logistic-map activation.
// Round 2: weights in SHARED memory (Blackwell has no cbank operands; LDC floor=8
// killed the __constant__ version), LDS.128 broadcast reads (4 weights / LDS),
// __launch_bounds__(128,1) so h[64]+acc[64] stay register-resident (no spills).

#define RCONST 3.82843f

__device__ __forceinline__ float act(float x) {
    x = cosf(x) * 0.5f + 0.5f;
    x = RCONST * x * (1.0f - x);
    x = RCONST * x * (1.0f - x);
    return x;
}

struct SW {
    float W1[128];
    float b1[64];
    float W2[4096];
    float b2[64];
    float W3[4096];
    float b3[64];
    float W4[64];
    float b4;
};

// One 64x64 layer: acc[j] += h[k] * W[j*64+k], weights via float4 shared loads.
// Both loops fully unrolled so h[] and acc[] stay in registers.
__device__ __forceinline__ void layer64(float h[64], const float4* __restrict__ Wv,
                                        const float* __restrict__ b) {
    float acc[64];
#pragma unroll
    for (int j = 0; j < 64; ++j) acc[j] = b[j];
#pragma unroll
    for (int k4 = 0; k4 < 16; ++k4) {
        const float h0 = h[4 * k4 + 0];
        const float h1 = h[4 * k4 + 1];
        const float h2 = h[4 * k4 + 2];
        const float h3 = h[4 * k4 + 3];
#pragma unroll
        for (int j = 0; j < 64; ++j) {
            const float4 w = Wv[j * 16 + k4];  // W[j][4k4 .. 4k4+3], warp-uniform -> LDS broadcast
            acc[j] = fmaf(h0, w.x, fmaf(h1, w.y, fmaf(h2, w.z, fmaf(h3, w.w, acc[j]))));
        }
    }
#pragma unroll
    for (int j = 0; j < 64; ++j) h[j] = act(acc[j]);
}

__global__ void __launch_bounds__(128, 1) Model_17188459119206_kernel(
    const float* __restrict__ x,
    const float* __restrict__ gW1, const float* __restrict__ gb1,
    const float* __restrict__ gW2, const float* __restrict__ gb2,
    const float* __restrict__ gW3, const float* __restrict__ gb3,
    const float* __restrict__ gW4, const float* __restrict__ gb4,
    float* __restrict__ out, int n) {
    __shared__ SW s;

    const int t = threadIdx.x;
    // Cooperative weight staging (vectorized where it matters: W2/W3).
    {
        const float4* g2 = reinterpret_cast<const float4*>(gW2);
        const float4* g3 = reinterpret_cast<const float4*>(gW3);
        float4* s2 = reinterpret_cast<float4*>(s.W2);
        float4* s3 = reinterpret_cast<float4*>(s.W3);
#pragma unroll
        for (int i = t; i < 1024; i += 128) {
            s2[i] = g2[i];
            s3[i] = g3[i];
        }
        if (t < 128) s.W1[t] = gW1[t];
        if (t < 64) {
            s.b1[t] = gb1[t];
            s.b2[t] = gb2[t];
            s.b3[t] = gb3[t];
            s.W4[t] = gW4[t];
        }
        if (t == 0) s.b4 = gb4[0];
    }
    __syncthreads();

    const int i = blockIdx.x * 128 + t;
    if (i >= n) return;

    const float2 p = reinterpret_cast<const float2*>(x)[i];

    float h[64];
    // Layer 1: 2 -> 64
#pragma unroll
    for (int j = 0; j < 64; ++j) {
        const float a = fmaf(s.W1[2 * j], p.x, fmaf(s.W1[2 * j + 1], p.y, s.b1[j]));
        h[j] = act(a);
    }

    // Layers 2,3: 64 -> 64
    layer64(h, reinterpret_cast<const float4*>(s.W2), s.b2);
    layer64(h, reinterpret_cast<const float4*>(s.W3), s.b3);

    // Layer 4: 64 -> 1
    float o = s.b4;
#pragma unroll
    for (int k = 0; k < 64; ++k) o = fmaf(h[k], s.W4[k], o);
    out[i] = act(o);
}

extern "C" void kernel_launch(void* const* d_in, const int* in_sizes, int n_in,
                              void* d_out, int out_size) {
    const float* x = (const float*)d_in[0];
    const int n = in_sizes[0] / 2;  // x is [N, 2]

    const int threads = 128;
    const int blocks = (n + threads - 1) / threads;
    Model_17188459119206_kernel<<<blocks, threads>>>(
        x,
        (const float*)d_in[1], (const float*)d_in[2],
        (const float*)d_in[3], (const float*)d_in[4],
        (const float*)d_in[5], (const float*)d_in[6],
        (const float*)d_in[7], (const float*)d_in[8],
        (float*)d_out, n);
}

// round 7
// speedup vs baseline: 29.9525x; 3.7220x over previous
#include <cuda_runtime.h>

// Fused MLP [N,2]->64->64->64->1, chaotic logistic-map activation.
// Round 3: fma.rn.f32x2 packed math (PTX-only FFMA2), transposed smem weights
// (stride 68: 16B-aligned rows, 4-way-max staging conflicts), __cosf activation.

#define RCONST 3.82843f

__device__ __forceinline__ float act(float x) {
    x = __cosf(x) * 0.5f + 0.5f;
    float t = RCONST * x;          // R*x
    x = fmaf(-t, x, t);            // R*x*(1-x)
    t = RCONST * x;
    x = fmaf(-t, x, t);
    return x;
}

#define WSTRIDE 68  // words per transposed row: 64 data + 4 pad (16B-aligned, breaks bank conflicts)

struct SW {
    float W2t[64 * WSTRIDE];  // W2t[k*WSTRIDE + j] = W2[j][k]
    float W3t[64 * WSTRIDE];
    float W1[128];
    float b1[64];
    float b2[64];
    float b3[64];
    float W4[64];
    float b4;
};

// 64x64 layer, packed: acc pair (2q,2q+1) over outputs, fma.rn.f32x2.
__device__ __forceinline__ void layer64p(float h[64], const float* __restrict__ Wt,
                                         const float* __restrict__ b) {
    unsigned long long acc[32];
#pragma unroll
    for (int q = 0; q < 32; ++q)
        asm("mov.b64 %0, {%1, %2};" : "=l"(acc[q]) : "f"(b[2 * q]), "f"(b[2 * q + 1]));

#pragma unroll
    for (int k = 0; k < 64; ++k) {
        unsigned long long hk2;
        asm("mov.b64 %0, {%1, %1};" : "=l"(hk2) : "f"(h[k]));
        const ulonglong2* row = reinterpret_cast<const ulonglong2*>(Wt + k * WSTRIDE);
#pragma unroll
        for (int q4 = 0; q4 < 16; ++q4) {
            const ulonglong2 w = row[q4];  // warp-uniform LDS.128 broadcast: 4 weights, 2 pairs
            asm("fma.rn.f32x2 %0, %1, %2, %0;" : "+l"(acc[2 * q4])     : "l"(hk2), "l"(w.x));
            asm("fma.rn.f32x2 %0, %1, %2, %0;" : "+l"(acc[2 * q4 + 1]) : "l"(hk2), "l"(w.y));
        }
    }
#pragma unroll
    for (int q = 0; q < 32; ++q) {
        float lo, hi;
        asm("mov.b64 {%0, %1}, %2;" : "=f"(lo), "=f"(hi) : "l"(acc[q]));
        h[2 * q]     = act(lo);
        h[2 * q + 1] = act(hi);
    }
}

__global__ void __launch_bounds__(128, 2) Model_17188459119206_kernel(
    const float* __restrict__ x,
    const float* __restrict__ gW1, const float* __restrict__ gb1,
    const float* __restrict__ gW2, const float* __restrict__ gb2,
    const float* __restrict__ gW3, const float* __restrict__ gb3,
    const float* __restrict__ gW4, const float* __restrict__ gb4,
    float* __restrict__ out, int n) {
    __shared__ SW s;
    const int t = threadIdx.x;

    // Stage weights. W2/W3 transposed: coalesced global reads, <=4-way smem write conflicts.
#pragma unroll
    for (int m = t; m < 4096; m += 128) {
        const int j = m >> 6, k = m & 63;
        s.W2t[k * WSTRIDE + j] = gW2[m];
        s.W3t[k * WSTRIDE + j] = gW3[m];
    }
    if (t < 128) s.W1[t] = gW1[t];
    if (t < 64) {
        s.b1[t] = gb1[t];
        s.b2[t] = gb2[t];
        s.b3[t] = gb3[t];
        s.W4[t] = gW4[t];
    }
    if (t == 0) s.b4 = gb4[0];
    __syncthreads();

    const int i = blockIdx.x * 128 + t;
    if (i >= n) return;

    const float2 p = reinterpret_cast<const float2*>(x)[i];

    float h[64];
    // Layer 1: 2 -> 64
#pragma unroll
    for (int j = 0; j < 64; ++j)
        h[j] = act(fmaf(s.W1[2 * j], p.x, fmaf(s.W1[2 * j + 1], p.y, s.b1[j])));

    // Layers 2,3: 64 -> 64 packed
    layer64p(h, s.W2t, s.b2);
    layer64p(h, s.W3t, s.b3);

    // Layer 4: 64 -> 1
    float o = s.b4;
#pragma unroll
    for (int k = 0; k < 64; ++k) o = fmaf(h[k], s.W4[k], o);
    out[i] = act(o);
}

extern "C" void kernel_launch(void* const* d_in, const int* in_sizes, int n_in,
                              void* d_out, int out_size) {
    const float* x = (const float*)d_in[0];
    const int n = in_sizes[0] / 2;  // x is [N, 2]

    const int threads = 128;
    const int blocks = (n + threads - 1) / threads;
    Model_17188459119206_kernel<<<blocks, threads>>>(
        x,
        (const float*)d_in[1], (const float*)d_in[2],
        (const float*)d_in[3], (const float*)d_in[4],
        (const float*)d_in[5], (const float*)d_in[6],
        (const float*)d_in[7], (const float*)d_in[8],
        (float*)d_out, n);
}

// round 9
// speedup vs baseline: 30.6562x; 1.0235x over previous
#include <cuda_runtime.h>

// Fused MLP [N,2]->64->64->64->1, chaotic logistic-map activation.
// Round 7: __launch_bounds__(128,3) for 3 blocks/SM (12 warps), h kept packed
// f32x2 across layers, activation rewritten via x(1-x)=0.25(1-cos^2) so iter1
// is one packed FMA; all act math packed (2 MUFU + 5 packed ops per pair).

#define RCONST 3.82843f
#define WSTRIDE 68  // 64 + 4 pad words; row = 272B = 17*16B (16B aligned, conflict-breaking)

typedef unsigned long long u64t;

__device__ __forceinline__ u64t pack2(float a, float b) {
    u64t r;
    asm("mov.b64 %0, {%1, %2};" : "=l"(r) : "f"(a), "f"(b));
    return r;
}

// Packed activation on a pair of pre-activations.
// ref: x = cos(a)*0.5+0.5; x = R x (1-x) twice.
// iter1 exact rewrite: R*x*(1-x) = R*0.25*(1 - cos^2) = fma(c^2, -R/4, R/4)
__device__ __forceinline__ u64t act2(u64t a, u64t NQR, u64t QR, u64t PR, u64t NR) {
    float lo, hi;
    asm("mov.b64 {%0, %1}, %2;" : "=f"(lo), "=f"(hi) : "l"(a));
    lo = __cosf(lo);
    hi = __cosf(hi);
    u64t c, c2, x1, u, v, r;
    asm("mov.b64 %0, {%1, %2};" : "=l"(c) : "f"(lo), "f"(hi));
    asm("mul.rn.f32x2 %0, %1, %1;" : "=l"(c2) : "l"(c));
    asm("fma.rn.f32x2 %0, %1, %2, %3;" : "=l"(x1) : "l"(c2), "l"(NQR), "l"(QR));
    asm("mul.rn.f32x2 %0, %1, %2;" : "=l"(u) : "l"(x1), "l"(PR));   //  R*x1
    asm("mul.rn.f32x2 %0, %1, %2;" : "=l"(v) : "l"(x1), "l"(NR));   // -R*x1
    asm("fma.rn.f32x2 %0, %1, %2, %3;" : "=l"(r) : "l"(v), "l"(x1), "l"(u));  // R*x1 - R*x1^2
    return r;
}

struct SW {
    alignas(16) float W2t[64 * WSTRIDE];  // W2t[k*WSTRIDE + j] = W2[j][k]
    alignas(16) float W3t[64 * WSTRIDE];
    alignas(16) float W1c0[64];  // W1[j][0]
    alignas(16) float W1c1[64];  // W1[j][1]
    alignas(16) float b1[64];
    alignas(16) float b2[64];
    alignas(16) float b3[64];
    alignas(16) float W4[64];
    float b4;
};

// 64x64 layer: h2 packed over output pairs, acc packed over output pairs.
__device__ __forceinline__ void layer64p(u64t h2[32], const float* __restrict__ Wt,
                                         const float* __restrict__ b,
                                         u64t NQR, u64t QR, u64t PR, u64t NR) {
    u64t acc[32];
    const u64t* bp = reinterpret_cast<const u64t*>(b);
#pragma unroll
    for (int q = 0; q < 32; ++q) acc[q] = bp[q];

#pragma unroll
    for (int q = 0; q < 32; ++q) {  // two k-values per q
        float h_lo, h_hi;
        asm("mov.b64 {%0, %1}, %2;" : "=f"(h_lo), "=f"(h_hi) : "l"(h2[q]));
        u64t ha, hb;
        asm("mov.b64 %0, {%1, %1};" : "=l"(ha) : "f"(h_lo));
        asm("mov.b64 %0, {%1, %1};" : "=l"(hb) : "f"(h_hi));
        const ulonglong2* rowA = reinterpret_cast<const ulonglong2*>(Wt + (2 * q) * WSTRIDE);
        const ulonglong2* rowB = reinterpret_cast<const ulonglong2*>(Wt + (2 * q + 1) * WSTRIDE);
#pragma unroll
        for (int p = 0; p < 16; ++p) {
            const ulonglong2 wa = rowA[p];  // warp-uniform LDS.128 broadcast
            asm("fma.rn.f32x2 %0, %1, %2, %0;" : "+l"(acc[2 * p])     : "l"(ha), "l"(wa.x));
            asm("fma.rn.f32x2 %0, %1, %2, %0;" : "+l"(acc[2 * p + 1]) : "l"(ha), "l"(wa.y));
            const ulonglong2 wb = rowB[p];
            asm("fma.rn.f32x2 %0, %1, %2, %0;" : "+l"(acc[2 * p])     : "l"(hb), "l"(wb.x));
            asm("fma.rn.f32x2 %0, %1, %2, %0;" : "+l"(acc[2 * p + 1]) : "l"(hb), "l"(wb.y));
        }
    }
#pragma unroll
    for (int q = 0; q < 32; ++q) h2[q] = act2(acc[q], NQR, QR, PR, NR);
}

__global__ void __launch_bounds__(128, 3) Model_17188459119206_kernel(
    const float* __restrict__ x,
    const float* __restrict__ gW1, const float* __restrict__ gb1,
    const float* __restrict__ gW2, const float* __restrict__ gb2,
    const float* __restrict__ gW3, const float* __restrict__ gb3,
    const float* __restrict__ gW4, const float* __restrict__ gb4,
    float* __restrict__ out, int n) {
    __shared__ SW s;
    const int t = threadIdx.x;

    // Stage weights (W2/W3 transposed; W1 split into columns for packed layer1).
#pragma unroll
    for (int m = t; m < 4096; m += 128) {
        const int j = m >> 6, k = m & 63;
        s.W2t[k * WSTRIDE + j] = gW2[m];
        s.W3t[k * WSTRIDE + j] = gW3[m];
    }
    if (t < 64) {
        s.W1c0[t] = gW1[2 * t];
        s.W1c1[t] = gW1[2 * t + 1];
        s.b1[t] = gb1[t];
        s.b2[t] = gb2[t];
        s.b3[t] = gb3[t];
        s.W4[t] = gW4[t];
    }
    if (t == 0) s.b4 = gb4[0];
    __syncthreads();

    const int i = blockIdx.x * 128 + t;
    if (i >= n) return;

    // Packed constants (warp-uniform -> UR)
    const u64t NQR = pack2(-0.25f * RCONST, -0.25f * RCONST);
    const u64t QR  = pack2(0.25f * RCONST, 0.25f * RCONST);
    const u64t PR  = pack2(RCONST, RCONST);
    const u64t NR  = pack2(-RCONST, -RCONST);

    const float2 p = reinterpret_cast<const float2*>(x)[i];
    u64t px2, py2;
    asm("mov.b64 %0, {%1, %1};" : "=l"(px2) : "f"(p.x));
    asm("mov.b64 %0, {%1, %1};" : "=l"(py2) : "f"(p.y));

    u64t h2[32];
    // Layer 1: 2 -> 64, packed over output pairs
    {
        const u64t* c0 = reinterpret_cast<const u64t*>(s.W1c0);
        const u64t* c1 = reinterpret_cast<const u64t*>(s.W1c1);
        const u64t* bp = reinterpret_cast<const u64t*>(s.b1);
#pragma unroll
        for (int q = 0; q < 32; ++q) {
            u64t a = bp[q];
            asm("fma.rn.f32x2 %0, %1, %2, %0;" : "+l"(a) : "l"(px2), "l"(c0[q]));
            asm("fma.rn.f32x2 %0, %1, %2, %0;" : "+l"(a) : "l"(py2), "l"(c1[q]));
            h2[q] = act2(a, NQR, QR, PR, NR);
        }
    }

    // Layers 2,3: 64 -> 64 packed
    layer64p(h2, s.W2t, s.b2, NQR, QR, PR, NR);
    layer64p(h2, s.W3t, s.b3, NQR, QR, PR, NR);

    // Layer 4: 64 -> 1 (packed dot, then scalar act)
    u64t d2 = pack2(0.0f, 0.0f);
    {
        const u64t* w4 = reinterpret_cast<const u64t*>(s.W4);
#pragma unroll
        for (int q = 0; q < 32; ++q)
            asm("fma.rn.f32x2 %0, %1, %2, %0;" : "+l"(d2) : "l"(h2[q]), "l"(w4[q]));
    }
    float dlo, dhi;
    asm("mov.b64 {%0, %1}, %2;" : "=f"(dlo), "=f"(dhi) : "l"(d2));
    float a = dlo + dhi + s.b4;
    // scalar act with the same algebraic rewrite
    const float c = __cosf(a);
    float x1 = fmaf(c * c, -0.25f * RCONST, 0.25f * RCONST);
    float r = fmaf(-RCONST * x1, x1, RCONST * x1);
    out[i] = r;
}

extern "C" void kernel_launch(void* const* d_in, const int* in_sizes, int n_in,
                              void* d_out, int out_size) {
    const float* x = (const float*)d_in[0];
    const int n = in_sizes[0] / 2;  // x is [N, 2]

    const int threads = 128;
    const int blocks = (n + threads - 1) / threads;
    Model_17188459119206_kernel<<<blocks, threads>>>(
        x,
        (const float*)d_in[1], (const float*)d_in[2],
        (const float*)d_in[3], (const float*)d_in[4],
        (const float*)d_in[5], (const float*)d_in[6],
        (const float*)d_in[7], (const float*)d_in[8],
        (float*)d_out, n);
}